// round 1
// baseline (speedup 1.0000x reference)
#include <cuda_runtime.h>
#include <cuda_bf16.h>

#define NN 20000
#define EE 320000
#define HH 8
#define DD 32
#define F1 128
#define HD 256   // H*D

// ---------------- scratch (device globals; no allocation allowed) -------------
__device__ float g_feat[NN * HD];      // [N, H*D] features of current layer
__device__ float g_el[NN * HH];
__device__ float g_er[NN * HH];
__device__ float g_w[EE * HH];         // exp(leaky(el[src]+er[dst]))
__device__ float g_h[NN * DD];         // layer-1 output (mean over heads of relu)
__device__ int   g_cnt[NN];
__device__ int   g_rowptr[NN + 1];
__device__ int   g_fill[NN];
__device__ int   g_eidx[EE];

// ---------------- CSR build ---------------------------------------------------
__global__ void zero_cnt_kernel() {
    int t = blockIdx.x * blockDim.x + threadIdx.x;
    if (t < NN) g_cnt[t] = 0;
}

__global__ void hist_kernel(const int* __restrict__ dst) {
    int e = blockIdx.x * blockDim.x + threadIdx.x;
    if (e < EE) atomicAdd(&g_cnt[dst[e]], 1);
}

// single-block exclusive scan over g_cnt -> g_rowptr / g_fill
__global__ void scan_kernel() {
    __shared__ int ssum[1024];
    int t = threadIdx.x;
    const int chunk = (NN + 1023) / 1024;  // 20
    int b = t * chunk;
    int e = min(b + chunk, NN);
    int s = 0;
    for (int i = b; i < e; i++) s += g_cnt[i];
    ssum[t] = s;
    __syncthreads();
    for (int off = 1; off < 1024; off <<= 1) {
        int v = (t >= off) ? ssum[t - off] : 0;
        __syncthreads();
        ssum[t] += v;
        __syncthreads();
    }
    int pref = (t > 0) ? ssum[t - 1] : 0;
    for (int i = b; i < e; i++) {
        g_rowptr[i] = pref;
        g_fill[i]   = pref;
        pref += g_cnt[i];
    }
    if (t == 1023) g_rowptr[NN] = ssum[1023];
}

__global__ void scatter_kernel(const int* __restrict__ dst) {
    int e = blockIdx.x * blockDim.x + threadIdx.x;
    if (e < EE) {
        int p = atomicAdd(&g_fill[dst[e]], 1);
        g_eidx[p] = e;
    }
}

// ---------------- GEMM + attention logits -------------------------------------
// feat = X @ W  (X:[n,K], W:[K,256]);  el/er = head-wise dot with al/ar.
// One block of 256 threads; thread j owns output column j; 4 rows per iteration.
template <int K>
__global__ void gemm_attn_kernel(const float* __restrict__ X,
                                 const float* __restrict__ W,
                                 const float* __restrict__ al,
                                 const float* __restrict__ ar,
                                 float* __restrict__ feat,
                                 float* __restrict__ el,
                                 float* __restrict__ er,
                                 int n) {
    constexpr int PAD = K + 4;          // 132 or 36 -> conflict-free LDS.128
    extern __shared__ float sh[];
    float* Wsh = sh;                    // [256][PAD], transposed: Wsh[j][k]
    float* Xsh = sh + 256 * PAD;        // [4][K]

    int tid = threadIdx.x;              // = output column j
    for (int idx = tid; idx < K * 256; idx += 256) {
        int k = idx >> 8, j = idx & 255;
        Wsh[j * PAD + k] = W[idx];
    }
    float alv = al[tid];
    float arv = ar[tid];
    int h = tid >> 5, lane = tid & 31;
    const float* wp = &Wsh[tid * PAD];
    __syncthreads();

    for (int r0 = blockIdx.x * 4; r0 < n; r0 += gridDim.x * 4) {
        int nr = min(4, n - r0);
        __syncthreads();
        for (int idx = tid; idx < nr * K; idx += 256)
            Xsh[idx] = X[(size_t)r0 * K + idx];
        __syncthreads();

        float acc0 = 0.f, acc1 = 0.f, acc2 = 0.f, acc3 = 0.f;
#pragma unroll
        for (int k = 0; k < K; k += 4) {
            float4 wv = *(const float4*)(wp + k);
#pragma unroll
            for (int kk = 0; kk < 4; kk++) {
                float wk = (&wv.x)[kk];
                acc0 = fmaf(Xsh[0 * K + k + kk], wk, acc0);
                acc1 = fmaf(Xsh[1 * K + k + kk], wk, acc1);
                acc2 = fmaf(Xsh[2 * K + k + kk], wk, acc2);
                acc3 = fmaf(Xsh[3 * K + k + kk], wk, acc3);
            }
        }
        float accs[4] = {acc0, acc1, acc2, acc3};
#pragma unroll
        for (int r = 0; r < 4; r++) {
            if (r >= nr) break;
            float v = accs[r];
            feat[(size_t)(r0 + r) * HD + tid] = v;
            float e1 = v * alv, e2 = v * arv;
#pragma unroll
            for (int off = 16; off; off >>= 1) {
                e1 += __shfl_xor_sync(0xffffffffu, e1, off);
                e2 += __shfl_xor_sync(0xffffffffu, e2, off);
            }
            if (lane == 0) {
                el[(r0 + r) * HH + h] = e1;
                er[(r0 + r) * HH + h] = e2;
            }
        }
    }
}

// ---------------- edge weights -------------------------------------------------
__global__ void edge_w_kernel(const int* __restrict__ src,
                              const int* __restrict__ dst) {
    int t = blockIdx.x * blockDim.x + threadIdx.x;
    if (t >= EE * HH) return;
    int e = t >> 3, h = t & 7;
    float v = g_el[src[e] * HH + h] + g_er[dst[e] * HH + h];
    v = v > 0.f ? v : 0.2f * v;
    g_w[t] = __expf(v);
}

// ---------------- aggregation (warp per dst node) ------------------------------
// out[node][lane] = epilogue over heads of ( sum_e w*feat[src] / sum_e w + bias )
template <bool RELU_BEFORE_MEAN>
__global__ void agg_kernel(const int* __restrict__ src,
                           const float* __restrict__ bias,
                           float* __restrict__ out) {
    int node = blockIdx.x * (blockDim.x >> 5) + (threadIdx.x >> 5);
    if (node >= NN) return;
    int lane = threadIdx.x & 31;
    int beg = g_rowptr[node], end = g_rowptr[node + 1];

    float acc[HH], den[HH];
#pragma unroll
    for (int h = 0; h < HH; h++) { acc[h] = 0.f; den[h] = 0.f; }

    for (int i = beg; i < end; i++) {
        int eid = g_eidx[i];
        int s = src[eid];
        const float* fp = g_feat + (size_t)s * HD + lane;
        const float* wp = g_w + eid * HH;
#pragma unroll
        for (int h = 0; h < HH; h++) {
            float wv = wp[h];
            den[h] += wv;
            acc[h] = fmaf(wv, fp[h * DD], acc[h]);
        }
    }
    float sum = 0.f;
#pragma unroll
    for (int h = 0; h < HH; h++) {
        float v = (den[h] > 0.f) ? (acc[h] / den[h]) : 0.f;
        v += bias[h * DD + lane];
        if (RELU_BEFORE_MEAN) v = fmaxf(v, 0.f);
        sum += v;
    }
    out[node * DD + lane] = sum * 0.125f;
}

// ---------------- launcher -----------------------------------------------------
extern "C" void kernel_launch(void* const* d_in, const int* in_sizes, int n_in,
                              void* d_out, int out_size) {
    const float* x   = (const float*)d_in[0];
    const int*   src = (const int*)d_in[1];
    const int*   dst = (const int*)d_in[2];
    const float* W1  = (const float*)d_in[3];
    const float* al1 = (const float*)d_in[4];
    const float* ar1 = (const float*)d_in[5];
    const float* b1  = (const float*)d_in[6];
    const float* W2  = (const float*)d_in[7];
    const float* al2 = (const float*)d_in[8];
    const float* ar2 = (const float*)d_in[9];
    const float* b2  = (const float*)d_in[10];
    float* out = (float*)d_out;

    float *feat, *el, *er, *hbuf;
    cudaGetSymbolAddress((void**)&feat, g_feat);
    cudaGetSymbolAddress((void**)&el, g_el);
    cudaGetSymbolAddress((void**)&er, g_er);
    cudaGetSymbolAddress((void**)&hbuf, g_h);

    // CSR build (shared by both layers)
    zero_cnt_kernel<<<(NN + 255) / 256, 256>>>();
    hist_kernel<<<(EE + 255) / 256, 256>>>(dst);
    scan_kernel<<<1, 1024>>>();
    scatter_kernel<<<(EE + 255) / 256, 256>>>(dst);

    // layer 1
    {
        constexpr int smem = (256 * (F1 + 4) + 4 * F1) * sizeof(float);
        cudaFuncSetAttribute(gemm_attn_kernel<F1>,
                             cudaFuncAttributeMaxDynamicSharedMemorySize, smem);
        gemm_attn_kernel<F1><<<148, 256, smem>>>(x, W1, al1, ar1, feat, el, er, NN);
        edge_w_kernel<<<(EE * HH + 255) / 256, 256>>>(src, dst);
        agg_kernel<true><<<(NN + 7) / 8, 256>>>(src, b1, hbuf);
    }
    // layer 2
    {
        constexpr int smem = (256 * (DD + 4) + 4 * DD) * sizeof(float);
        cudaFuncSetAttribute(gemm_attn_kernel<DD>,
                             cudaFuncAttributeMaxDynamicSharedMemorySize, smem);
        gemm_attn_kernel<DD><<<592, 256, smem>>>(hbuf, W2, al2, ar2, feat, el, er, NN);
        edge_w_kernel<<<(EE * HH + 255) / 256, 256>>>(src, dst);
        agg_kernel<false><<<(NN + 7) / 8, 256>>>(src, b2, out);
    }
}

// round 2
// speedup vs baseline: 1.1471x; 1.1471x over previous
#include <cuda_runtime.h>
#include <cuda_bf16.h>

#define NN 20000
#define EE 320000
#define HH 8
#define DD 32
#define F1 128
#define HD 256   // H*D

// ---------------- scratch (device globals; no allocation allowed) -------------
__device__ float g_feat[NN * HD];      // [N, dim*8+head] transposed features
__device__ float g_el[NN * HH];
__device__ float g_er[NN * HH];
__device__ float g_h[NN * DD];         // layer-1 output
__device__ float g_Wp[F1 * HD];        // column-permuted weights (reused per layer)
__device__ float g_alp[HD];
__device__ float g_arp[HD];
__device__ int   g_cnt[NN];
__device__ int   g_rowptr[NN + 1];
__device__ int   g_fill[NN];
__device__ int   g_esrc[EE];           // src node per CSR slot

// ---------------- CSR build ---------------------------------------------------
__global__ void zero_cnt_kernel() {
    int t = blockIdx.x * blockDim.x + threadIdx.x;
    if (t < NN) g_cnt[t] = 0;
}

__global__ void hist_kernel(const int* __restrict__ dst) {
    int e = blockIdx.x * blockDim.x + threadIdx.x;
    if (e < EE) atomicAdd(&g_cnt[dst[e]], 1);
}

// single-block exclusive scan over g_cnt -> g_rowptr / g_fill
__global__ void scan_kernel() {
    __shared__ int ssum[1024];
    int t = threadIdx.x;
    const int chunk = (NN + 1023) / 1024;  // 20
    int b = t * chunk;
    int e = min(b + chunk, NN);
    int s = 0;
    for (int i = b; i < e; i++) s += g_cnt[i];
    ssum[t] = s;
    __syncthreads();
    for (int off = 1; off < 1024; off <<= 1) {
        int v = (t >= off) ? ssum[t - off] : 0;
        __syncthreads();
        ssum[t] += v;
        __syncthreads();
    }
    int pref = (t > 0) ? ssum[t - 1] : 0;
    for (int i = b; i < e; i++) {
        g_rowptr[i] = pref;
        g_fill[i]   = pref;
        pref += g_cnt[i];
    }
    if (t == 1023) g_rowptr[NN] = ssum[1023];
}

__global__ void scatter_kernel(const int* __restrict__ src,
                               const int* __restrict__ dst) {
    int e = blockIdx.x * blockDim.x + threadIdx.x;
    if (e < EE) {
        int p = atomicAdd(&g_fill[dst[e]], 1);
        g_esrc[p] = src[e];
    }
}

// ---------------- weight column permutation -----------------------------------
// logical col L(j) = (j&7)*32 + (j>>3)  => feat_t element j = (dim=j>>3, head=j&7)
__global__ void perm_kernel(const float* __restrict__ W,
                            const float* __restrict__ al,
                            const float* __restrict__ ar, int K) {
    int t = blockIdx.x * blockDim.x + threadIdx.x;
    if (t < K * HD) {
        int k = t >> 8, j = t & 255;
        int L = ((j & 7) << 5) | (j >> 3);
        g_Wp[k * HD + j] = W[k * HD + L];
    }
    if (t < HD) {
        int L = ((t & 7) << 5) | (t >> 3);
        g_alp[t] = al[L];
        g_arp[t] = ar[L];
    }
}

// ---------------- GEMM (persistent, smem-resident W) --------------------------
// feat[row][j] = sum_k X[row][k] * Wp[k][j].  8 rows per tile, 1 col per thread.
template <int K>
__global__ void gemm_kernel(const float* __restrict__ X,
                            float* __restrict__ feat, int n) {
    constexpr int PAD = K + 4;
    extern __shared__ float sh[];
    float* Wsh = sh;                    // [256][PAD] (col-major per thread)
    float* Xsh = sh + 256 * PAD;        // [8][K]
    int tid = threadIdx.x;

    for (int idx = tid; idx < K * HD; idx += 256) {
        int k = idx >> 8, j = idx & 255;
        Wsh[j * PAD + k] = g_Wp[idx];
    }
    const float* wp = Wsh + tid * PAD;
    __syncthreads();

    for (int t = blockIdx.x; t * 8 < n; t += gridDim.x) {
        int r0 = t * 8;
        __syncthreads();
        for (int idx = tid; idx < 8 * K; idx += 256)
            Xsh[idx] = X[(size_t)r0 * K + idx];
        __syncthreads();

        float acc[8];
#pragma unroll
        for (int r = 0; r < 8; r++) acc[r] = 0.f;

#pragma unroll 8
        for (int k = 0; k < K; k += 4) {
            float4 wv = *(const float4*)(wp + k);
#pragma unroll
            for (int r = 0; r < 8; r++) {
                float4 xv = *(const float4*)(Xsh + r * K + k);
                acc[r] = fmaf(xv.x, wv.x, acc[r]);
                acc[r] = fmaf(xv.y, wv.y, acc[r]);
                acc[r] = fmaf(xv.z, wv.z, acc[r]);
                acc[r] = fmaf(xv.w, wv.w, acc[r]);
            }
        }
#pragma unroll
        for (int r = 0; r < 8; r++)
            feat[(size_t)(r0 + r) * HD + tid] = acc[r];
    }
}

// ---------------- attention logits (warp per node) ----------------------------
__global__ void elr_kernel(int n) {
    int gid = blockIdx.x * blockDim.x + threadIdx.x;
    int node = gid >> 5;
    if (node >= n) return;
    int lane = gid & 31;
    const float4* fp = (const float4*)(g_feat + (size_t)node * HD + lane * 8);
    float4 f0 = fp[0], f1 = fp[1];
    const float4* ap = (const float4*)(g_alp + lane * 8);
    float4 a0 = ap[0], a1 = ap[1];
    const float4* bp = (const float4*)(g_arp + lane * 8);
    float4 b0 = bp[0], b1 = bp[1];
    float pa[8] = {f0.x * a0.x, f0.y * a0.y, f0.z * a0.z, f0.w * a0.w,
                   f1.x * a1.x, f1.y * a1.y, f1.z * a1.z, f1.w * a1.w};
    float pb[8] = {f0.x * b0.x, f0.y * b0.y, f0.z * b0.z, f0.w * b0.w,
                   f1.x * b1.x, f1.y * b1.y, f1.z * b1.z, f1.w * b1.w};
#pragma unroll
    for (int h = 0; h < 8; h++) {
#pragma unroll
        for (int off = 16; off; off >>= 1) {
            pa[h] += __shfl_xor_sync(0xffffffffu, pa[h], off);
            pb[h] += __shfl_xor_sync(0xffffffffu, pb[h], off);
        }
    }
    if (lane == 0) {
        float* elp = g_el + node * HH;
        float* erp = g_er + node * HH;
        elp[0] = pa[0]; elp[1] = pa[1]; elp[2] = pa[2]; elp[3] = pa[3];
        elp[4] = pa[4]; elp[5] = pa[5]; elp[6] = pa[6]; elp[7] = pa[7];
        erp[0] = pb[0]; erp[1] = pb[1]; erp[2] = pb[2]; erp[3] = pb[3];
        erp[4] = pb[4]; erp[5] = pb[5]; erp[6] = pb[6]; erp[7] = pb[7];
    }
}

// ---------------- aggregation (warp per dst node, fused softmax) --------------
template <bool RELU_BEFORE_MEAN>
__global__ void agg_kernel(const float* __restrict__ bias,
                           float* __restrict__ out) {
    int node = blockIdx.x * (blockDim.x >> 5) + (threadIdx.x >> 5);
    if (node >= NN) return;
    int lane = threadIdx.x & 31;
    int hh = lane & 7;
    float er_l = g_er[node * HH + hh];
    int beg = g_rowptr[node], end = g_rowptr[node + 1];

    float acc[8];
#pragma unroll
    for (int h = 0; h < 8; h++) acc[h] = 0.f;
    float den_l = 0.f;

    int s = (beg < end) ? g_esrc[beg] : 0;
    for (int i = beg; i < end; i++) {
        int s_next = (i + 1 < end) ? g_esrc[i + 1] : 0;
        float elv = __ldg(g_el + s * HH + hh);
        const float4* fp = (const float4*)(g_feat + (size_t)s * HD + lane * 8);
        float4 f0 = fp[0], f1 = fp[1];
        float v = elv + er_l;
        v = v > 0.f ? v : 0.2f * v;
        float e = __expf(v);
        den_l += e;
        float w0 = __shfl_sync(0xffffffffu, e, 0);
        float w1 = __shfl_sync(0xffffffffu, e, 1);
        float w2 = __shfl_sync(0xffffffffu, e, 2);
        float w3 = __shfl_sync(0xffffffffu, e, 3);
        float w4 = __shfl_sync(0xffffffffu, e, 4);
        float w5 = __shfl_sync(0xffffffffu, e, 5);
        float w6 = __shfl_sync(0xffffffffu, e, 6);
        float w7 = __shfl_sync(0xffffffffu, e, 7);
        acc[0] = fmaf(w0, f0.x, acc[0]);
        acc[1] = fmaf(w1, f0.y, acc[1]);
        acc[2] = fmaf(w2, f0.z, acc[2]);
        acc[3] = fmaf(w3, f0.w, acc[3]);
        acc[4] = fmaf(w4, f1.x, acc[4]);
        acc[5] = fmaf(w5, f1.y, acc[5]);
        acc[6] = fmaf(w6, f1.z, acc[6]);
        acc[7] = fmaf(w7, f1.w, acc[7]);
        s = s_next;
    }
    float sum = 0.f;
#pragma unroll
    for (int h = 0; h < 8; h++) {
        float dh = __shfl_sync(0xffffffffu, den_l, h);
        float r = (dh > 0.f) ? acc[h] / dh : 0.f;
        r += bias[h * DD + lane];
        if (RELU_BEFORE_MEAN) r = fmaxf(r, 0.f);
        sum += r;
    }
    out[node * DD + lane] = sum * 0.125f;
}

// ---------------- launcher -----------------------------------------------------
extern "C" void kernel_launch(void* const* d_in, const int* in_sizes, int n_in,
                              void* d_out, int out_size) {
    const float* x   = (const float*)d_in[0];
    const int*   src = (const int*)d_in[1];
    const int*   dst = (const int*)d_in[2];
    const float* W1  = (const float*)d_in[3];
    const float* al1 = (const float*)d_in[4];
    const float* ar1 = (const float*)d_in[5];
    const float* b1  = (const float*)d_in[6];
    const float* W2  = (const float*)d_in[7];
    const float* al2 = (const float*)d_in[8];
    const float* ar2 = (const float*)d_in[9];
    const float* b2  = (const float*)d_in[10];
    float* out = (float*)d_out;

    float *feat, *hbuf;
    cudaGetSymbolAddress((void**)&feat, g_feat);
    cudaGetSymbolAddress((void**)&hbuf, g_h);

    // CSR build (launches 1-4)
    zero_cnt_kernel<<<(NN + 255) / 256, 256>>>();
    hist_kernel<<<(EE + 255) / 256, 256>>>(dst);
    scan_kernel<<<1, 1024>>>();
    scatter_kernel<<<(EE + 255) / 256, 256>>>(src, dst);

    // layer 1  (launch 6 = gemm1, for ncu -s 5 -c 1 capture)
    {
        constexpr int smem = (256 * (F1 + 4) + 8 * F1) * sizeof(float);
        cudaFuncSetAttribute(gemm_kernel<F1>,
                             cudaFuncAttributeMaxDynamicSharedMemorySize, smem);
        perm_kernel<<<(F1 * HD + 255) / 256, 256>>>(W1, al1, ar1, F1);
        gemm_kernel<F1><<<148, 256, smem>>>(x, feat, NN);
        elr_kernel<<<(NN * 32 + 255) / 256, 256>>>(NN);
        agg_kernel<true><<<(NN + 7) / 8, 256>>>(b1, hbuf);
    }
    // layer 2
    {
        constexpr int smem = (256 * (DD + 4) + 8 * DD) * sizeof(float);
        cudaFuncSetAttribute(gemm_kernel<DD>,
                             cudaFuncAttributeMaxDynamicSharedMemorySize, smem);
        perm_kernel<<<(DD * HD + 255) / 256, 256>>>(W2, al2, ar2, DD);
        gemm_kernel<DD><<<592, 256, smem>>>(hbuf, feat, NN);
        elr_kernel<<<(NN * 32 + 255) / 256, 256>>>(NN);
        agg_kernel<false><<<(NN + 7) / 8, 256>>>(b2, out);
    }
}

// round 3
// speedup vs baseline: 1.2887x; 1.1235x over previous
#include <cuda_runtime.h>
#include <cuda_bf16.h>

#define NN 20000
#define EE 320000
#define HH 8
#define DD 32
#define F1 128
#define HD 256   // H*D
#define TR 72    // gemm row tile (8 rowgroups x 9 rows)

// ---------------- scratch (device globals; no allocation allowed) -------------
__device__ float g_feat[NN * HD];      // [N, dim*8+head] transposed features
__device__ float g_el[NN * HH];
__device__ float g_er[NN * HH];
__device__ float g_h[NN * DD];         // layer-1 output
__device__ float g_Wp[F1 * HD];        // column-permuted weights (reused per layer)
__device__ float g_alp[HD];
__device__ float g_arp[HD];
__device__ int   g_cnt[NN];
__device__ int   g_rowptr[NN + 1];
__device__ int   g_fill[NN];
__device__ int   g_esrc[EE];           // src node per CSR slot

// ---------------- CSR build ---------------------------------------------------
__global__ void zero_cnt_kernel() {
    int t = blockIdx.x * blockDim.x + threadIdx.x;
    if (t < NN) g_cnt[t] = 0;
}

__global__ void hist_kernel(const int* __restrict__ dst) {
    int e = blockIdx.x * blockDim.x + threadIdx.x;
    if (e < EE) atomicAdd(&g_cnt[dst[e]], 1);
}

// single-block exclusive scan over g_cnt -> g_rowptr / g_fill
__global__ void scan_kernel() {
    __shared__ int ssum[1024];
    int t = threadIdx.x;
    const int chunk = (NN + 1023) / 1024;  // 20
    int b = t * chunk;
    int e = min(b + chunk, NN);
    int s = 0;
    for (int i = b; i < e; i++) s += g_cnt[i];
    ssum[t] = s;
    __syncthreads();
    for (int off = 1; off < 1024; off <<= 1) {
        int v = (t >= off) ? ssum[t - off] : 0;
        __syncthreads();
        ssum[t] += v;
        __syncthreads();
    }
    int pref = (t > 0) ? ssum[t - 1] : 0;
    for (int i = b; i < e; i++) {
        g_rowptr[i] = pref;
        g_fill[i]   = pref;
        pref += g_cnt[i];
    }
    if (t == 1023) g_rowptr[NN] = ssum[1023];
}

__global__ void scatter_kernel(const int* __restrict__ src,
                               const int* __restrict__ dst) {
    int e = blockIdx.x * blockDim.x + threadIdx.x;
    if (e < EE) {
        int p = atomicAdd(&g_fill[dst[e]], 1);
        g_esrc[p] = src[e];
    }
}

// ---------------- weight column permutation -----------------------------------
// logical col L(j) = (j&7)*32 + (j>>3)  => feat_t element j = (dim=j>>3, head=j&7)
__global__ void perm_kernel(const float* __restrict__ W,
                            const float* __restrict__ al,
                            const float* __restrict__ ar, int K) {
    int t = blockIdx.x * blockDim.x + threadIdx.x;
    if (t < K * HD) {
        int k = t >> 8, j = t & 255;
        int L = ((j & 7) << 5) | (j >> 3);
        g_Wp[k * HD + j] = W[k * HD + L];
    }
    if (t < HD) {
        int L = ((t & 7) << 5) | (t >> 3);
        g_alp[t] = al[L];
        g_arp[t] = ar[L];
    }
}

// ---------------- GEMM: register-tiled, 4 cols x 9 rows per thread ------------
// feat[row][j] = sum_k X[row][k] * Wp[k][j].
// Block: 512 threads, tile = 72 rows x 256 cols. Thread (t): cols 4*(t&63),
// rowgroup (t>>6)*9. All lanes of a warp share the rowgroup -> X LDS broadcast.
template <int K>
__global__ __launch_bounds__(512) void gemm_kernel(const float* __restrict__ X,
                                                   float* __restrict__ feat,
                                                   int n) {
    extern __shared__ float sh[];
    float* Wsh = sh;            // [K][256] k-major
    float* Xsh = sh + K * HD;   // [TR][K]
    int tid = threadIdx.x;

    for (int idx = tid; idx < K * HD; idx += 512)
        Wsh[idx] = g_Wp[idx];

    int r0 = blockIdx.x * TR;
    int nr = min(TR, n - r0);
    for (int idx = tid; idx < nr * K; idx += 512)
        Xsh[idx] = X[(size_t)r0 * K + idx];
    __syncthreads();

    int col = (tid & 63) * 4;
    int rg = (tid >> 6) * 9;

    float acc[9][4];
#pragma unroll
    for (int r = 0; r < 9; r++)
#pragma unroll
        for (int c = 0; c < 4; c++) acc[r][c] = 0.f;

#pragma unroll 4
    for (int k = 0; k < K; k += 4) {
        float4 w0 = *(const float4*)(Wsh + (k + 0) * HD + col);
        float4 w1 = *(const float4*)(Wsh + (k + 1) * HD + col);
        float4 w2 = *(const float4*)(Wsh + (k + 2) * HD + col);
        float4 w3 = *(const float4*)(Wsh + (k + 3) * HD + col);
#pragma unroll
        for (int r = 0; r < 9; r++) {
            float4 xv = *(const float4*)(Xsh + (rg + r) * K + k);
            acc[r][0] = fmaf(xv.x, w0.x, acc[r][0]);
            acc[r][1] = fmaf(xv.x, w0.y, acc[r][1]);
            acc[r][2] = fmaf(xv.x, w0.z, acc[r][2]);
            acc[r][3] = fmaf(xv.x, w0.w, acc[r][3]);
            acc[r][0] = fmaf(xv.y, w1.x, acc[r][0]);
            acc[r][1] = fmaf(xv.y, w1.y, acc[r][1]);
            acc[r][2] = fmaf(xv.y, w1.z, acc[r][2]);
            acc[r][3] = fmaf(xv.y, w1.w, acc[r][3]);
            acc[r][0] = fmaf(xv.z, w2.x, acc[r][0]);
            acc[r][1] = fmaf(xv.z, w2.y, acc[r][1]);
            acc[r][2] = fmaf(xv.z, w2.z, acc[r][2]);
            acc[r][3] = fmaf(xv.z, w2.w, acc[r][3]);
            acc[r][0] = fmaf(xv.w, w3.x, acc[r][0]);
            acc[r][1] = fmaf(xv.w, w3.y, acc[r][1]);
            acc[r][2] = fmaf(xv.w, w3.z, acc[r][2]);
            acc[r][3] = fmaf(xv.w, w3.w, acc[r][3]);
        }
    }

#pragma unroll
    for (int r = 0; r < 9; r++) {
        int row = rg + r;
        if (row < nr) {
            float4 v = make_float4(acc[r][0], acc[r][1], acc[r][2], acc[r][3]);
            *(float4*)(feat + (size_t)(r0 + row) * HD + col) = v;
        }
    }
}

// ---------------- attention logits (warp per node) ----------------------------
__global__ void elr_kernel(int n) {
    int gid = blockIdx.x * blockDim.x + threadIdx.x;
    int node = gid >> 5;
    if (node >= n) return;
    int lane = gid & 31;
    const float4* fp = (const float4*)(g_feat + (size_t)node * HD + lane * 8);
    float4 f0 = fp[0], f1 = fp[1];
    const float4* ap = (const float4*)(g_alp + lane * 8);
    float4 a0 = ap[0], a1 = ap[1];
    const float4* bp = (const float4*)(g_arp + lane * 8);
    float4 b0 = bp[0], b1 = bp[1];
    float pa[8] = {f0.x * a0.x, f0.y * a0.y, f0.z * a0.z, f0.w * a0.w,
                   f1.x * a1.x, f1.y * a1.y, f1.z * a1.z, f1.w * a1.w};
    float pb[8] = {f0.x * b0.x, f0.y * b0.y, f0.z * b0.z, f0.w * b0.w,
                   f1.x * b1.x, f1.y * b1.y, f1.z * b1.z, f1.w * b1.w};
#pragma unroll
    for (int h = 0; h < 8; h++) {
#pragma unroll
        for (int off = 16; off; off >>= 1) {
            pa[h] += __shfl_xor_sync(0xffffffffu, pa[h], off);
            pb[h] += __shfl_xor_sync(0xffffffffu, pb[h], off);
        }
    }
    if (lane == 0) {
        float* elp = g_el + node * HH;
        float* erp = g_er + node * HH;
        elp[0] = pa[0]; elp[1] = pa[1]; elp[2] = pa[2]; elp[3] = pa[3];
        elp[4] = pa[4]; elp[5] = pa[5]; elp[6] = pa[6]; elp[7] = pa[7];
        erp[0] = pb[0]; erp[1] = pb[1]; erp[2] = pb[2]; erp[3] = pb[3];
        erp[4] = pb[4]; erp[5] = pb[5]; erp[6] = pb[6]; erp[7] = pb[7];
    }
}

// ---------------- aggregation (warp per dst node, fused softmax) --------------
template <bool RELU_BEFORE_MEAN>
__global__ void agg_kernel(const float* __restrict__ bias,
                           float* __restrict__ out) {
    int node = blockIdx.x * (blockDim.x >> 5) + (threadIdx.x >> 5);
    if (node >= NN) return;
    int lane = threadIdx.x & 31;
    int hh = lane & 7;
    float er_l = g_er[node * HH + hh];
    int beg = g_rowptr[node], end = g_rowptr[node + 1];

    float acc[8];
#pragma unroll
    for (int h = 0; h < 8; h++) acc[h] = 0.f;
    float den_l = 0.f;

    int i = beg;
    for (; i + 2 <= end; i += 2) {
        int s0 = g_esrc[i];
        int s1 = g_esrc[i + 1];
        float el0 = __ldg(g_el + s0 * HH + hh);
        float el1 = __ldg(g_el + s1 * HH + hh);
        const float4* fp0 = (const float4*)(g_feat + (size_t)s0 * HD + lane * 8);
        const float4* fp1 = (const float4*)(g_feat + (size_t)s1 * HD + lane * 8);
        float4 a0 = fp0[0], a1 = fp0[1];
        float4 c0 = fp1[0], c1 = fp1[1];
        float v0 = el0 + er_l; v0 = v0 > 0.f ? v0 : 0.2f * v0;
        float v1 = el1 + er_l; v1 = v1 > 0.f ? v1 : 0.2f * v1;
        float e0 = __expf(v0);
        float e1 = __expf(v1);
        den_l += e0 + e1;
#pragma unroll
        for (int h = 0; h < 8; h++) {
            float w0 = __shfl_sync(0xffffffffu, e0, h);
            float w1 = __shfl_sync(0xffffffffu, e1, h);
            float f0 = (h < 4) ? (&a0.x)[h] : (&a1.x)[h - 4];
            float f1 = (h < 4) ? (&c0.x)[h] : (&c1.x)[h - 4];
            acc[h] = fmaf(w0, f0, acc[h]);
            acc[h] = fmaf(w1, f1, acc[h]);
        }
    }
    if (i < end) {
        int s = g_esrc[i];
        float elv = __ldg(g_el + s * HH + hh);
        const float4* fp = (const float4*)(g_feat + (size_t)s * HD + lane * 8);
        float4 a0 = fp[0], a1 = fp[1];
        float v = elv + er_l; v = v > 0.f ? v : 0.2f * v;
        float e = __expf(v);
        den_l += e;
#pragma unroll
        for (int h = 0; h < 8; h++) {
            float w = __shfl_sync(0xffffffffu, e, h);
            float f = (h < 4) ? (&a0.x)[h] : (&a1.x)[h - 4];
            acc[h] = fmaf(w, f, acc[h]);
        }
    }

    float sum = 0.f;
#pragma unroll
    for (int h = 0; h < 8; h++) {
        float dh = __shfl_sync(0xffffffffu, den_l, h);
        float r = (dh > 0.f) ? acc[h] / dh : 0.f;
        r += bias[h * DD + lane];
        if (RELU_BEFORE_MEAN) r = fmaxf(r, 0.f);
        sum += r;
    }
    out[node * DD + lane] = sum * 0.125f;
}

// ---------------- launcher -----------------------------------------------------
extern "C" void kernel_launch(void* const* d_in, const int* in_sizes, int n_in,
                              void* d_out, int out_size) {
    const float* x   = (const float*)d_in[0];
    const int*   src = (const int*)d_in[1];
    const int*   dst = (const int*)d_in[2];
    const float* W1  = (const float*)d_in[3];
    const float* al1 = (const float*)d_in[4];
    const float* ar1 = (const float*)d_in[5];
    const float* b1  = (const float*)d_in[6];
    const float* W2  = (const float*)d_in[7];
    const float* al2 = (const float*)d_in[8];
    const float* ar2 = (const float*)d_in[9];
    const float* b2  = (const float*)d_in[10];
    float* out = (float*)d_out;

    float *feat, *hbuf;
    cudaGetSymbolAddress((void**)&feat, g_feat);
    cudaGetSymbolAddress((void**)&hbuf, g_h);

    const int NT = (NN + TR - 1) / TR;  // 278 tiles

    // CSR build
    zero_cnt_kernel<<<(NN + 255) / 256, 256>>>();
    hist_kernel<<<(EE + 255) / 256, 256>>>(dst);
    scan_kernel<<<1, 1024>>>();
    scatter_kernel<<<(EE + 255) / 256, 256>>>(src, dst);

    // layer 1
    {
        constexpr int smem = (F1 * HD + TR * F1) * sizeof(float);
        cudaFuncSetAttribute(gemm_kernel<F1>,
                             cudaFuncAttributeMaxDynamicSharedMemorySize, smem);
        perm_kernel<<<(F1 * HD + 255) / 256, 256>>>(W1, al1, ar1, F1);
        gemm_kernel<F1><<<NT, 512, smem>>>(x, feat, NN);
        elr_kernel<<<(NN * 32 + 255) / 256, 256>>>(NN);
        agg_kernel<true><<<(NN + 7) / 8, 256>>>(b1, hbuf);
    }
    // layer 2
    {
        constexpr int smem = (DD * HD + TR * DD) * sizeof(float);
        cudaFuncSetAttribute(gemm_kernel<DD>,
                             cudaFuncAttributeMaxDynamicSharedMemorySize, smem);
        perm_kernel<<<(DD * HD + 255) / 256, 256>>>(W2, al2, ar2, DD);
        gemm_kernel<DD><<<NT, 512, smem>>>(hbuf, feat, NN);
        elr_kernel<<<(NN * 32 + 255) / 256, 256>>>(NN);
        agg_kernel<false><<<(NN + 7) / 8, 256>>>(b2, out);
    }
}